// round 5
// baseline (speedup 1.0000x reference)
#include <cuda_runtime.h>
#include <cstdint>

// ElementUpdate: out[n,:] = h_prev[n,:] + W[z[n]] @ m_curr[n,:]
// N=16384, D=128, S=119, z sorted. mma.sync m16n8k8 tf32 (compute_103-safe).
// R5: R3 config (TILE_M=64, full-N W, 2 CTAs/SM) + ldmatrix.x4 fragment loads
// (5 LDSM vs 20 LDS per k-step) + segment-0 W prefill merged with A fill.

static constexpr int D = 128;
static constexpr int TILE_M = 64;
static constexpr int NT = 256;
static constexpr int APAD = 132;               // conflict-free float stride
static constexpr int HDR = 1024;
static constexpr int A_BYTES = TILE_M * APAD * 4;   // 33792
static constexpr int W_BYTES = D * APAD * 4;        // 67584
static constexpr int SMEM_BYTES = HDR + A_BYTES + W_BYTES;  // 102400 -> 2 CTAs/SM

__device__ __forceinline__ uint32_t f2tf32(float f) {
    uint32_t r;
    asm("cvt.rna.tf32.f32 %0, %1;" : "=r"(r) : "f"(f));
    return r;
}

__device__ __forceinline__ uint32_t smem_u32(const void* p) {
    uint32_t a;
    asm("{ .reg .u64 t; cvta.to.shared.u64 t, %1; cvt.u32.u64 %0, t; }" : "=r"(a) : "l"(p));
    return a;
}

__device__ __forceinline__ void ldsm4(uint32_t& r0, uint32_t& r1, uint32_t& r2, uint32_t& r3,
                                      uint32_t addr) {
    asm volatile("ldmatrix.sync.aligned.m8n8.x4.shared.b16 {%0,%1,%2,%3}, [%4];"
                 : "=r"(r0), "=r"(r1), "=r"(r2), "=r"(r3) : "r"(addr));
}

__device__ __forceinline__ void mma_tf32(float* d, const uint32_t* a,
                                         uint32_t b0, uint32_t b1) {
    asm volatile(
        "mma.sync.aligned.m16n8k8.row.col.f32.tf32.tf32.f32 "
        "{%0,%1,%2,%3}, {%4,%5,%6,%7}, {%8,%9}, {%0,%1,%2,%3};"
        : "+f"(d[0]), "+f"(d[1]), "+f"(d[2]), "+f"(d[3])
        : "r"(a[0]), "r"(a[1]), "r"(a[2]), "r"(a[3]), "r"(b0), "r"(b1));
}

__global__ void __launch_bounds__(NT, 2)
element_update_kernel(const float* __restrict__ h_prev,
                      const float* __restrict__ m_curr,
                      const int* __restrict__ atom_types,
                      const float* __restrict__ weight,
                      float* __restrict__ out) {
    extern __shared__ __align__(16) char smem[];
    const int tid = threadIdx.x;
    const int lane = tid & 31;
    const int wid = tid >> 5;
    const int R0 = blockIdx.x * TILE_M;

    int* sCnt  = (int*)(smem + 0);
    int* sOff  = (int*)(smem + 16);
    int* sNseg = (int*)(smem + 32);
    int* sRow  = (int*)(smem + 64);     // up to TILE_M+1 entries
    int* sSpec = (int*)(smem + 384);    // up to TILE_M entries
    uint32_t* sA = (uint32_t*)(smem + HDR);
    uint32_t* sW = (uint32_t*)(smem + HDR + A_BYTES);

    // ---- species-segment scan over TILE_M sorted z values (warps 0-1) ----
    bool bd = false; int wpre = 0, zr = 0;
    if (tid < TILE_M) {
        zr = atom_types[R0 + tid];
        int zp = (tid == 0) ? -1 : atom_types[R0 + tid - 1];
        bd = (zp != zr);
        unsigned msk = __ballot_sync(0xffffffffu, bd);
        wpre = __popc(msk & ((1u << lane) - 1u));
        if (lane == 0) sCnt[wid] = __popc(msk);
    }

    // ---- A tile fill + W[s0] prefill (segment 0's species is known now) ----
    const int s0 = atom_types[R0];
    for (int i = tid; i < TILE_M * (D / 4); i += NT) {
        int r = i >> 5, c4 = (i & 31) << 2;
        float4 v = *(const float4*)(m_curr + (size_t)(R0 + r) * D + c4);
        uint4 u;
        u.x = f2tf32(v.x); u.y = f2tf32(v.y); u.z = f2tf32(v.z); u.w = f2tf32(v.w);
        *(uint4*)(sA + r * APAD + c4) = u;
    }
    {
        const float* wsrc = weight + (size_t)s0 * (D * D);
        for (int i = tid; i < D * (D / 4); i += NT) {
            int r = i >> 5, c4 = (i & 31) << 2;
            float4 v = *(const float4*)(wsrc + (size_t)r * D + c4);
            uint4 u;
            u.x = f2tf32(v.x); u.y = f2tf32(v.y); u.z = f2tf32(v.z); u.w = f2tf32(v.w);
            *(uint4*)(sW + r * APAD + c4) = u;
        }
    }
    __syncthreads();
    if (tid == 0) {
        int c0 = sCnt[0], c1 = sCnt[1];
        sOff[0] = 0; sOff[1] = c0;
        *sNseg = c0 + c1;
        sRow[c0 + c1] = TILE_M;
    }
    __syncthreads();
    if (tid < TILE_M && bd) {
        int i = sOff[wid] + wpre;
        sRow[i] = tid;
        sSpec[i] = zr;
    }
    __syncthreads();
    const int nseg = *sNseg;

    // ---- warp geometry: rows [16*wr,+16) x cols [64*wc,+64) ----
    const int wr = wid >> 1;     // 0..3
    const int wc = wid & 1;      // 0..1
    const int rlo = wr * 16;
    const int lr = lane >> 2;    // 0..7
    const int lc = lane & 3;     // 0..3

    float acc[8][4];
    #pragma unroll
    for (int nt = 0; nt < 8; nt++)
        #pragma unroll
        for (int j = 0; j < 4; j++) acc[nt][j] = 0.f;

    // ldmatrix per-thread row addresses (b16 m8n8, b32-element reinterpretation)
    // A x4: m0=(rowblk0,kh0)->a0, m1=(rowblk1,kh0)->a1, m2=(rowblk0,kh4)->a2, m3=(rowblk1,kh4)->a3
    //   rowblk = (lane>>3)&1, kh = ((lane>>4)&1)*4
    const uint32_t sAu = smem_u32(sA);
    const uint32_t sWu = smem_u32(sW);
    const uint32_t aRow = (uint32_t)(rlo + (lane & 7) + ((lane >> 3) & 1) * 8);
    const uint32_t aLd0 = sAu + (aRow * APAD + ((lane >> 4) & 1) * 4) * 4;
    // B x4 (pair p of nt): m0=(nt=2p,kh0)->b0, m1=(2p,kh4)->b1, m2=(2p+1,kh0), m3=(2p+1,kh4)
    //   rowblk(+8 rows) = lane>>4, kh = ((lane>>3)&1)*4
    const uint32_t bRow = (uint32_t)(wc * 64 + ((lane >> 4) & 1) * 8 + (lane & 7));
    const uint32_t bLd0 = sWu + (bRow * APAD + ((lane >> 3) & 1) * 4) * 4;

    for (int seg = 0; seg < nseg; seg++) {
        const int a = sRow[seg];
        const int b = sRow[seg + 1];

        if (seg > 0) {
            const int s = sSpec[seg];
            __syncthreads();   // previous segment's compute done before W overwrite
            const float* wsrc = weight + (size_t)s * (D * D);
            for (int i = tid; i < D * (D / 4); i += NT) {
                int r = i >> 5, c4 = (i & 31) << 2;
                float4 v = *(const float4*)(wsrc + (size_t)r * D + c4);
                uint4 u;
                u.x = f2tf32(v.x); u.y = f2tf32(v.y); u.z = f2tf32(v.z); u.w = f2tf32(v.w);
                *(uint4*)(sW + r * APAD + c4) = u;
            }
            __syncthreads();
        }

        if (b > rlo && a < rlo + 16) {
            const int r0 = rlo + lr;
            const uint32_t am0 = (r0 >= a && r0 < b) ? 0xffffffffu : 0u;
            const uint32_t am1 = (r0 + 8 >= a && r0 + 8 < b) ? 0xffffffffu : 0u;

            #pragma unroll 4
            for (int ks = 0; ks < 16; ks++) {
                const uint32_t koff = (uint32_t)(ks * 32);   // 8 words
                uint32_t aF[4];
                ldsm4(aF[0], aF[1], aF[2], aF[3], aLd0 + koff);
                aF[0] &= am0; aF[1] &= am1; aF[2] &= am0; aF[3] &= am1;
                #pragma unroll
                for (int p = 0; p < 4; p++) {
                    uint32_t bF[4];
                    ldsm4(bF[0], bF[1], bF[2], bF[3],
                          bLd0 + (uint32_t)(p * 16 * APAD * 4) + koff);
                    mma_tf32(acc[2 * p + 0], aF, bF[0], bF[1]);
                    mma_tf32(acc[2 * p + 1], aF, bF[2], bF[3]);
                }
            }
        }
    }

    // ---- epilogue: acc + h_prev -> out (coalesced float2, 32B sectors) ----
    #pragma unroll
    for (int h = 0; h < 2; h++) {
        const int r = R0 + rlo + 8 * h + lr;
        const float* hp = h_prev + (size_t)r * D;
        float* op = out + (size_t)r * D;
        #pragma unroll
        for (int nt = 0; nt < 8; nt++) {
            const int c = wc * 64 + 8 * nt + lc * 2;
            float2 hv = *(const float2*)(hp + c);
            float2 o;
            o.x = hv.x + acc[nt][2 * h + 0];
            o.y = hv.y + acc[nt][2 * h + 1];
            *(float2*)(op + c) = o;
        }
    }
}

extern "C" void kernel_launch(void* const* d_in, const int* in_sizes, int n_in,
                              void* d_out, int out_size) {
    const float* h_prev     = (const float*)d_in[0];
    const float* m_curr     = (const float*)d_in[1];
    const int*   atom_types = (const int*)d_in[2];
    const float* weight     = (const float*)d_in[3];
    float* out = (float*)d_out;

    int n_nodes = in_sizes[0] / D;   // 16384
    int grid = n_nodes / TILE_M;     // 256

    cudaFuncSetAttribute(element_update_kernel,
                         cudaFuncAttributeMaxDynamicSharedMemorySize, SMEM_BYTES);
    element_update_kernel<<<grid, NT, SMEM_BYTES>>>(h_prev, m_curr, atom_types,
                                                    weight, out);
}

// round 7
// speedup vs baseline: 1.4269x; 1.4269x over previous
#include <cuda_runtime.h>
#include <cstdint>

// ElementUpdate: out[n,:] = h_prev[n,:] + W[z[n]] @ m_curr[n,:]
// N=16384, D=128, S=119, z sorted. mma.sync m16n8k8 tf32 (compute_103-safe).
// R7: R6 async pipeline with the h_prev copy fixed (4 chunks/thread, was 1).
// CTA = 64 rows x 64 out-cols. cp.async fills raw fp32 SMEM (A once; W double-
// buffered per sorted-species segment; h_prev slice prefetched as the final
// pseudo-segment). tf32 cvt.rna in the fragment path. Scalar conflict-free LDS.

static constexpr int D = 128;
static constexpr int TILE_M = 64;
static constexpr int TILE_N = 64;
static constexpr int NT = 256;
static constexpr int APAD = 132;               // conflict-free float stride
static constexpr int HDR = 1024;
static constexpr int BUF_BYTES = TILE_M * APAD * 4;          // 33792
static constexpr int SMEM_BYTES = HDR + 3 * BUF_BYTES;       // 102400 -> 2 CTAs/SM

__device__ __forceinline__ uint32_t f2tf32(float f) {
    uint32_t r;
    asm("cvt.rna.tf32.f32 %0, %1;" : "=r"(r) : "f"(f));
    return r;
}

__device__ __forceinline__ uint32_t smem_u32(const void* p) {
    uint32_t a;
    asm("{ .reg .u64 t; cvta.to.shared.u64 t, %1; cvt.u32.u64 %0, t; }" : "=r"(a) : "l"(p));
    return a;
}

__device__ __forceinline__ void cpa16(uint32_t dst, const void* src) {
    asm volatile("cp.async.ca.shared.global [%0], [%1], 16;" :: "r"(dst), "l"(src));
}
#define CP_COMMIT() asm volatile("cp.async.commit_group;" ::: "memory")
#define CP_WAIT(n)  asm volatile("cp.async.wait_group %0;" :: "n"(n) : "memory")

__device__ __forceinline__ void mma_tf32(float* d, const uint32_t* a,
                                         uint32_t b0, uint32_t b1) {
    asm volatile(
        "mma.sync.aligned.m16n8k8.row.col.f32.tf32.tf32.f32 "
        "{%0,%1,%2,%3}, {%4,%5,%6,%7}, {%8,%9}, {%0,%1,%2,%3};"
        : "+f"(d[0]), "+f"(d[1]), "+f"(d[2]), "+f"(d[3])
        : "r"(a[0]), "r"(a[1]), "r"(a[2]), "r"(a[3]), "r"(b0), "r"(b1));
}

__global__ void __launch_bounds__(NT, 2)
element_update_kernel(const float* __restrict__ h_prev,
                      const float* __restrict__ m_curr,
                      const int* __restrict__ atom_types,
                      const float* __restrict__ weight,
                      float* __restrict__ out) {
    extern __shared__ __align__(16) char smem[];
    const int tid = threadIdx.x;
    const int lane = tid & 31;
    const int wid = tid >> 5;
    const int R0 = (blockIdx.x >> 1) * TILE_M;   // node-row tile
    const int N0 = (blockIdx.x & 1) * TILE_N;    // out-col half

    int* sCnt  = (int*)(smem + 0);
    int* sNseg = (int*)(smem + 32);
    int* sRow  = (int*)(smem + 64);     // up to TILE_M+1
    int* sSpec = (int*)(smem + 384);    // up to TILE_M
    float* fA = (float*)(smem + HDR);
    float* fW0 = (float*)(smem + HDR + BUF_BYTES);
    float* fW1 = (float*)(smem + HDR + 2 * BUF_BYTES);
    float* fWbuf[2] = {fW0, fW1};

    const uint32_t sbase = smem_u32(smem);
    const uint32_t aU = sbase + HDR;
    const uint32_t wU[2] = {aU + (uint32_t)BUF_BYTES, aU + 2u * (uint32_t)BUF_BYTES};

    // first species (serial dependency for W0 prefetch)
    const int s0 = atom_types[R0];

    // ---- job A: m_curr rows [R0,R0+64) -> fA (raw fp32), 8 cp.async/thread ----
    {
        const float* src = m_curr + (size_t)R0 * D;
        #pragma unroll
        for (int j = 0; j < 8; j++) {
            int t = tid + j * NT;
            int r = t >> 5, c4 = (t & 31) << 2;
            cpa16(aU + (uint32_t)(r * APAD + c4) * 4u, src + r * D + c4);
        }
    }
    CP_COMMIT();
    // ---- job 0: W[s0] rows [N0,N0+64) -> fW0 ----
    {
        const float* src = weight + (size_t)s0 * (D * D) + (size_t)N0 * D;
        #pragma unroll
        for (int j = 0; j < 8; j++) {
            int t = tid + j * NT;
            int r = t >> 5, c4 = (t & 31) << 2;
            cpa16(wU[0] + (uint32_t)(r * APAD + c4) * 4u, src + r * D + c4);
        }
    }
    CP_COMMIT();

    // ---- species-segment scan over TILE_M sorted z (warps 0-1), overlapped ----
    bool bd = false; int wpre = 0, zr = 0;
    if (tid < TILE_M) {
        zr = atom_types[R0 + tid];
        int zp = (tid == 0) ? -1 : atom_types[R0 + tid - 1];
        bd = (zp != zr);
        unsigned msk = __ballot_sync(0xffffffffu, bd);
        wpre = __popc(msk & ((1u << lane) - 1u));
        if (lane == 0) sCnt[wid] = __popc(msk);
    }
    __syncthreads();
    if (tid == 0) {
        int c0 = sCnt[0], c1 = sCnt[1];
        sCnt[2] = c0;                 // offset for warp 1
        *sNseg = c0 + c1;
        sRow[c0 + c1] = TILE_M;
    }
    __syncthreads();
    if (tid < TILE_M && bd) {
        int i = (wid ? sCnt[2] : 0) + wpre;
        sRow[i] = tid;
        sSpec[i] = zr;
    }
    __syncthreads();
    const int nseg = *sNseg;

    // ---- job i (1..nseg): i<nseg -> W[sSpec[i]]; i==nseg -> h_prev slice ----
    auto issue_job = [&](int i) {
        uint32_t dU = wU[i & 1];
        if (i < nseg) {
            const float* src = weight + (size_t)sSpec[i] * (D * D) + (size_t)N0 * D;
            #pragma unroll
            for (int j = 0; j < 8; j++) {
                int t = tid + j * NT;
                int r = t >> 5, c4 = (t & 31) << 2;
                cpa16(dU + (uint32_t)(r * APAD + c4) * 4u, src + r * D + c4);
            }
        } else {
            // h_prev rows [R0,R0+64), cols [N0,N0+64): 64 rows x 16 chunks
            // = 1024 chunks -> 4 per thread (R6 bug: had 1 per thread)
            const float* src = h_prev + (size_t)R0 * D + N0;
            #pragma unroll
            for (int j = 0; j < 4; j++) {
                int t = tid + j * NT;
                int r = t >> 4, c4 = (t & 15) << 2;
                cpa16(dU + (uint32_t)(r * APAD + c4) * 4u, src + r * D + c4);
            }
        }
        CP_COMMIT();
    };

    issue_job(1);
    CP_WAIT(1);        // A + W0 complete; job1 may be in flight
    __syncthreads();

    // ---- warp geometry: rows [16*wr,+16) x CTA-cols [32*wc,+32) ----
    const int wr = wid >> 1;     // 0..3
    const int wc = wid & 1;      // 0..1
    const int rlo = wr * 16;
    const int lr = lane >> 2;    // 0..7
    const int lc = lane & 3;     // 0..3

    float acc[4][4];
    #pragma unroll
    for (int nt = 0; nt < 4; nt++)
        #pragma unroll
        for (int j = 0; j < 4; j++) acc[nt][j] = 0.f;

    const float* pAbase = fA + (rlo + lr) * APAD + lc;

    for (int seg = 0; seg < nseg; seg++) {
        const int a = sRow[seg];
        const int b = sRow[seg + 1];
        const float* pBbase = fWbuf[seg & 1] + (wc * 32 + lr) * APAD + lc;

        if (b > rlo && a < rlo + 16) {
            const int r0 = rlo + lr;
            const uint32_t am0 = (r0 >= a && r0 < b) ? 0xffffffffu : 0u;
            const uint32_t am1 = (r0 + 8 >= a && r0 + 8 < b) ? 0xffffffffu : 0u;

            #pragma unroll 4
            for (int ks = 0; ks < 16; ks++) {
                const int k0 = ks * 8;
                uint32_t aF[4];
                const float* pA = pAbase + k0;
                aF[0] = f2tf32(pA[0]) & am0;
                aF[2] = f2tf32(pA[4]) & am0;
                aF[1] = f2tf32(pA[8 * APAD]) & am1;
                aF[3] = f2tf32(pA[8 * APAD + 4]) & am1;
                #pragma unroll
                for (int nt = 0; nt < 4; nt++) {
                    const float* pB = pBbase + nt * (8 * APAD) + k0;
                    uint32_t b0 = f2tf32(pB[0]);
                    uint32_t b1 = f2tf32(pB[4]);
                    mma_tf32(acc[nt], aF, b0, b1);
                }
            }
        }

        __syncthreads();                       // all warps done reading fWbuf[seg&1]
        if (seg + 2 <= nseg) { issue_job(seg + 2); CP_WAIT(1); }
        else                 { CP_WAIT(0); }
        __syncthreads();                       // next buffer (or h) visible
    }

    // ---- epilogue: acc + h (from smem) -> out, coalesced float2 ----
    const float* hbuf = fWbuf[nseg & 1];
    #pragma unroll
    for (int h = 0; h < 2; h++) {
        const int rl = rlo + 8 * h + lr;
        float* op = out + (size_t)(R0 + rl) * D + N0;
        #pragma unroll
        for (int nt = 0; nt < 4; nt++) {
            const int cl = wc * 32 + 8 * nt + lc * 2;
            float2 o;
            o.x = hbuf[rl * APAD + cl]     + acc[nt][2 * h + 0];
            o.y = hbuf[rl * APAD + cl + 1] + acc[nt][2 * h + 1];
            *(float2*)(op + cl) = o;
        }
    }
}

extern "C" void kernel_launch(void* const* d_in, const int* in_sizes, int n_in,
                              void* d_out, int out_size) {
    const float* h_prev     = (const float*)d_in[0];
    const float* m_curr     = (const float*)d_in[1];
    const int*   atom_types = (const int*)d_in[2];
    const float* weight     = (const float*)d_in[3];
    float* out = (float*)d_out;

    int n_nodes = in_sizes[0] / D;       // 16384
    int grid = (n_nodes / TILE_M) * 2;   // 512

    cudaFuncSetAttribute(element_update_kernel,
                         cudaFuncAttributeMaxDynamicSharedMemorySize, SMEM_BYTES);
    element_update_kernel<<<grid, NT, SMEM_BYTES>>>(h_prev, m_curr, atom_types,
                                                    weight, out);
}

// round 9
// speedup vs baseline: 2.0809x; 1.4583x over previous
#include <cuda_runtime.h>
#include <cuda_fp16.h>
#include <cstdint>

// ElementUpdate: out[n,:] = h_prev[n,:] + W[z[n]] @ m_curr[n,:]
// N=16384, D=128, S=119, z sorted.
// R9: R8 (fp16 m16n8k16 pivot) with the pack intrinsic fixed (cvt.rn.f16x2.f32).
// R3 skeleton: TILE_M=64, full-width W per sorted-species segment, sync fills,
// s0 prefill, masked-A fp32 accumulation, 2+ CTAs/SM.

static constexpr int D = 128;
static constexpr int TILE_M = 64;
static constexpr int NT = 256;
static constexpr int HPAD = 136;               // half-stride: 272B row, conflict-free
static constexpr int HDR = 1024;
static constexpr int A_BYTES = TILE_M * HPAD * 2;   // 17408
static constexpr int W_BYTES = D * HPAD * 2;        // 34816
static constexpr int SMEM_BYTES = HDR + A_BYTES + W_BYTES;  // 53248

__device__ __forceinline__ uint32_t pack_h2(float lo, float hi) {
    uint32_t r;
    asm("cvt.rn.f16x2.f32 %0, %1, %2;" : "=r"(r) : "f"(hi), "f"(lo));
    return r;
}

__device__ __forceinline__ void mma_f16(float* d, const uint32_t* a,
                                        uint32_t b0, uint32_t b1) {
    asm volatile(
        "mma.sync.aligned.m16n8k16.row.col.f32.f16.f16.f32 "
        "{%0,%1,%2,%3}, {%4,%5,%6,%7}, {%8,%9}, {%0,%1,%2,%3};"
        : "+f"(d[0]), "+f"(d[1]), "+f"(d[2]), "+f"(d[3])
        : "r"(a[0]), "r"(a[1]), "r"(a[2]), "r"(a[3]), "r"(b0), "r"(b1));
}

__global__ void __launch_bounds__(NT, 2)
element_update_kernel(const float* __restrict__ h_prev,
                      const float* __restrict__ m_curr,
                      const int* __restrict__ atom_types,
                      const float* __restrict__ weight,
                      float* __restrict__ out) {
    extern __shared__ __align__(16) char smem[];
    const int tid = threadIdx.x;
    const int lane = tid & 31;
    const int wid = tid >> 5;
    const int R0 = blockIdx.x * TILE_M;

    int* sCnt  = (int*)(smem + 0);
    int* sNseg = (int*)(smem + 32);
    int* sRow  = (int*)(smem + 64);     // up to TILE_M+1
    int* sSpec = (int*)(smem + 384);    // up to TILE_M
    __half* sA = (__half*)(smem + HDR);
    __half* sW = (__half*)(smem + HDR + A_BYTES);

    // ---- species-segment scan over TILE_M sorted z values (warps 0-1) ----
    bool bd = false; int wpre = 0, zr = 0;
    if (tid < TILE_M) {
        zr = atom_types[R0 + tid];
        int zp = (tid == 0) ? -1 : atom_types[R0 + tid - 1];
        bd = (zp != zr);
        unsigned msk = __ballot_sync(0xffffffffu, bd);
        wpre = __popc(msk & ((1u << lane) - 1u));
        if (lane == 0) sCnt[wid] = __popc(msk);
    }

    // ---- A fill (m_curr -> fp16) + W[s0] prefill, overlapped with scan ----
    const int s0 = atom_types[R0];
    #pragma unroll
    for (int j = 0; j < 8; j++) {
        int i = tid + j * NT;
        int r = i >> 5, c4 = (i & 31) << 2;
        float4 v = *(const float4*)(m_curr + (size_t)(R0 + r) * D + c4);
        uint2 u;
        u.x = pack_h2(v.x, v.y);
        u.y = pack_h2(v.z, v.w);
        *(uint2*)(sA + r * HPAD + c4) = u;
    }
    {
        const float* wsrc = weight + (size_t)s0 * (D * D);
        #pragma unroll
        for (int j = 0; j < 16; j++) {
            int i = tid + j * NT;
            int r = i >> 5, c4 = (i & 31) << 2;
            float4 v = *(const float4*)(wsrc + (size_t)r * D + c4);
            uint2 u;
            u.x = pack_h2(v.x, v.y);
            u.y = pack_h2(v.z, v.w);
            *(uint2*)(sW + r * HPAD + c4) = u;
        }
    }
    __syncthreads();
    if (tid == 0) {
        int c0 = sCnt[0], c1 = sCnt[1];
        sCnt[2] = c0;
        *sNseg = c0 + c1;
        sRow[c0 + c1] = TILE_M;
    }
    __syncthreads();
    if (tid < TILE_M && bd) {
        int i = (wid ? sCnt[2] : 0) + wpre;
        sRow[i] = tid;
        sSpec[i] = zr;
    }
    __syncthreads();
    const int nseg = *sNseg;

    // ---- warp geometry: rows [16*wr,+16) x cols [64*wc,+64) ----
    const int wr = wid >> 1;     // 0..3
    const int wc = wid & 1;      // 0..1
    const int rlo = wr * 16;
    const int lr = lane >> 2;    // 0..7
    const int lc = lane & 3;     // 0..3

    float acc[8][4];
    #pragma unroll
    for (int nt = 0; nt < 8; nt++)
        #pragma unroll
        for (int j = 0; j < 4; j++) acc[nt][j] = 0.f;

    // fragment base pointers (halves). k16-step ks: A k = ks*16 + lc*2 (+8 for a2/a3)
    const __half* pA0 = sA + (rlo + lr) * HPAD + lc * 2;          // row r
    const __half* pA1 = pA0 + 8 * HPAD;                           // row r+8
    const __half* pB0 = sW + (wc * 64 + lr) * HPAD + lc * 2;      // B: n = base+lr

    for (int seg = 0; seg < nseg; seg++) {
        const int a = sRow[seg];
        const int b = sRow[seg + 1];

        if (seg > 0) {
            const int s = sSpec[seg];
            __syncthreads();   // previous segment's compute done before W overwrite
            const float* wsrc = weight + (size_t)s * (D * D);
            #pragma unroll
            for (int j = 0; j < 16; j++) {
                int i = tid + j * NT;
                int r = i >> 5, c4 = (i & 31) << 2;
                float4 v = *(const float4*)(wsrc + (size_t)r * D + c4);
                uint2 u;
                u.x = pack_h2(v.x, v.y);
                u.y = pack_h2(v.z, v.w);
                *(uint2*)(sW + r * HPAD + c4) = u;
            }
            __syncthreads();
        }

        if (b > rlo && a < rlo + 16) {
            const int r0 = rlo + lr;
            const uint32_t am0 = (r0 >= a && r0 < b) ? 0xffffffffu : 0u;
            const uint32_t am1 = (r0 + 8 >= a && r0 + 8 < b) ? 0xffffffffu : 0u;

            #pragma unroll
            for (int ks = 0; ks < 8; ks++) {
                const int k0 = ks * 16;
                uint32_t aF[4];
                aF[0] = *(const uint32_t*)(pA0 + k0) & am0;
                aF[1] = *(const uint32_t*)(pA1 + k0) & am1;
                aF[2] = *(const uint32_t*)(pA0 + k0 + 8) & am0;
                aF[3] = *(const uint32_t*)(pA1 + k0 + 8) & am1;
                #pragma unroll
                for (int nt = 0; nt < 8; nt++) {
                    const __half* pB = pB0 + nt * (8 * HPAD) + k0;
                    uint32_t b0 = *(const uint32_t*)(pB);
                    uint32_t b1 = *(const uint32_t*)(pB + 8);
                    mma_f16(acc[nt], aF, b0, b1);
                }
            }
        }
    }

    // ---- epilogue: acc + h_prev -> out (coalesced float2, 32B sectors) ----
    #pragma unroll
    for (int h = 0; h < 2; h++) {
        const int r = R0 + rlo + 8 * h + lr;
        const float* hp = h_prev + (size_t)r * D;
        float* op = out + (size_t)r * D;
        #pragma unroll
        for (int nt = 0; nt < 8; nt++) {
            const int c = wc * 64 + 8 * nt + lc * 2;
            float2 hv = *(const float2*)(hp + c);
            float2 o;
            o.x = hv.x + acc[nt][2 * h + 0];
            o.y = hv.y + acc[nt][2 * h + 1];
            *(float2*)(op + c) = o;
        }
    }
}

extern "C" void kernel_launch(void* const* d_in, const int* in_sizes, int n_in,
                              void* d_out, int out_size) {
    const float* h_prev     = (const float*)d_in[0];
    const float* m_curr     = (const float*)d_in[1];
    const int*   atom_types = (const int*)d_in[2];
    const float* weight     = (const float*)d_in[3];
    float* out = (float*)d_out;

    int n_nodes = in_sizes[0] / D;   // 16384
    int grid = n_nodes / TILE_M;     // 256

    cudaFuncSetAttribute(element_update_kernel,
                         cudaFuncAttributeMaxDynamicSharedMemorySize, SMEM_BYTES);
    element_update_kernel<<<grid, NT, SMEM_BYTES>>>(h_prev, m_curr, atom_types,
                                                    weight, out);
}